// round 1
// baseline (speedup 1.0000x reference)
#include <cuda_runtime.h>

#define NPT   100   // points per batch element
#define KNN   10
#define XS    36    // padded row stride (floats) for [n][c] feature tiles, 144B = 16B aligned
#define NTHR  256

struct Ptrs {
    const float* obs;
    const float* W0; const float* W1; const float* W2; const float* W3; const float* W4;
    const float* W5; const float* W6; const float* W7; const float* W8; const float* W9;
    const float* s[9]; const float* t[9];
};

__device__ __forceinline__ float lrelu(float v) { return fmaxf(v, 0.2f * v); }
__device__ __forceinline__ float dot4(const float4 a, const float4 b) {
    return a.x * b.x + a.y * b.y + a.z * b.z + a.w * b.w;
}

// ---------------------------------------------------------------------------
// kNN: per-thread row (point), streaming top-10 selection (descending dist,
// ties -> smaller index, matching jax.lax.top_k semantics via strict >).
// dist[i][j] = 2*<xi,xj> - |xi|^2 - |xj|^2
// ---------------------------------------------------------------------------
__device__ void knn_stage(const float* __restrict__ xsrc, float* __restrict__ xx,
                          int* __restrict__ idx, int tid)
{
    if (tid < NPT) {
        const float* r = xsrc + tid * XS;
        float a = 0.f;
        #pragma unroll
        for (int c = 0; c < 32; ++c) a += r[c] * r[c];
        xx[tid] = a;
    }
    __syncthreads();
    if (tid < NPT) {
        float4 xi[8];
        const float4* r4 = (const float4*)(xsrc + tid * XS);
        #pragma unroll
        for (int q = 0; q < 8; ++q) xi[q] = r4[q];
        const float nxi = xx[tid];
        float v[KNN]; int id[KNN];
        #pragma unroll
        for (int p = 0; p < KNN; ++p) { v[p] = -3.4e38f; id[p] = 0; }
        for (int j = 0; j < NPT; ++j) {
            const float4* rj = (const float4*)(xsrc + j * XS);
            float dt = 0.f;
            #pragma unroll
            for (int q = 0; q < 8; ++q) dt += dot4(xi[q], rj[q]);
            float d = 2.f * dt - nxi - xx[j];
            if (d > v[KNN - 1]) {
                float dv = d; int di = j;
                #pragma unroll
                for (int p = 0; p < KNN; ++p) {
                    if (dv > v[p]) {
                        float tv = v[p]; int ti = id[p];
                        v[p] = dv; id[p] = di;
                        dv = tv; di = ti;
                    }
                }
            }
        }
        #pragma unroll
        for (int p = 0; p < KNN; ++p) idx[tid * KNN + p] = id[p];
    }
    __syncthreads();
}

// ---------------------------------------------------------------------------
// Dual-conv EdgeConv block:  y1 = lrelu(sa*(Wa.nbr + (Wb'-Wa).ctr) + ta)
//                            z  = W2.y1 ;  out = lrelu(sb*max_k(z) + tb)
// 200 active threads: (n, k-half of 5). ctr term precomputed into smem sbase.
// W2 applied transposed so z[o2] stays in unrolled registers while o1 is rolled.
// ---------------------------------------------------------------------------
__device__ void edge_dual(const float* __restrict__ xsrc, float* __restrict__ dest,
                          const int* __restrict__ idx,
                          const float* __restrict__ Wg  /*32x64*/,
                          const float* __restrict__ Wbg /*32x32*/,
                          const float* __restrict__ sa, const float* __restrict__ ta,
                          const float* __restrict__ sb, const float* __restrict__ tb,
                          float* __restrict__ scr, int tid)
{
    float* Wa    = scr;            // 1024
    float* Wd    = scr + 1024;     // 1024  (W[:,32:] - W[:,:32])
    float* Wbt   = scr + 2048;     // 1024  (transposed second conv)
    float* sbase = scr + 3072;     // 200*33 = 6600
    float* pm    = scr + 9672;     // 100*36 = 3600
    for (int i = tid; i < 1024; i += NTHR) {
        int o = i >> 5, c = i & 31;
        float wa = Wg[o * 64 + c];
        Wa[i] = wa;
        Wd[i] = Wg[o * 64 + 32 + c] - wa;
        Wbt[c * 32 + o] = Wbg[i];           // Wbt[o1*32+o2] = Wb[o2*32+o1]
    }
    __syncthreads();

    float4 m4[8];
    const bool act = tid < 2 * NPT;
    int n = 0;
    if (act) {
        n = tid % NPT;
        const int kh = tid / NPT;
        // hoisted center term
        float4 ctr[8];
        const float4* cr = (const float4*)(xsrc + n * XS);
        #pragma unroll
        for (int q = 0; q < 8; ++q) ctr[q] = cr[q];
        for (int o1 = 0; o1 < 32; ++o1) {
            const float4* wd = (const float4*)(Wd + o1 * 32);
            float acc = 0.f;
            #pragma unroll
            for (int q = 0; q < 8; ++q) acc += dot4(wd[q], ctr[q]);
            sbase[tid * 33 + o1] = acc;
        }
        #pragma unroll
        for (int q = 0; q < 8; ++q) m4[q] = make_float4(-3.4e38f, -3.4e38f, -3.4e38f, -3.4e38f);

        for (int kk = 0; kk < 5; ++kk) {
            const int j = idx[n * KNN + kh * 5 + kk];
            float4 nb[8];
            const float4* nr = (const float4*)(xsrc + j * XS);
            #pragma unroll
            for (int q = 0; q < 8; ++q) nb[q] = nr[q];
            float4 z4[8];
            #pragma unroll
            for (int q = 0; q < 8; ++q) z4[q] = make_float4(0.f, 0.f, 0.f, 0.f);
            for (int o1 = 0; o1 < 32; ++o1) {
                const float4* wa = (const float4*)(Wa + o1 * 32);
                float acc = sbase[tid * 33 + o1];
                #pragma unroll
                for (int q = 0; q < 8; ++q) acc += dot4(wa[q], nb[q]);
                const float y1 = lrelu(fmaf(sa[o1], acc, ta[o1]));
                const float4* wb = (const float4*)(Wbt + o1 * 32);
                #pragma unroll
                for (int q = 0; q < 8; ++q) {
                    float4 w = wb[q];
                    z4[q].x = fmaf(w.x, y1, z4[q].x);
                    z4[q].y = fmaf(w.y, y1, z4[q].y);
                    z4[q].z = fmaf(w.z, y1, z4[q].z);
                    z4[q].w = fmaf(w.w, y1, z4[q].w);
                }
            }
            #pragma unroll
            for (int q = 0; q < 8; ++q) {
                m4[q].x = fmaxf(m4[q].x, z4[q].x);
                m4[q].y = fmaxf(m4[q].y, z4[q].y);
                m4[q].z = fmaxf(m4[q].z, z4[q].z);
                m4[q].w = fmaxf(m4[q].w, z4[q].w);
            }
        }
        if (kh == 1) {
            float4* pr = (float4*)(pm + n * XS);
            #pragma unroll
            for (int q = 0; q < 8; ++q) pr[q] = m4[q];
        }
    }
    __syncthreads();
    if (tid < NPT) {
        const float4* pr = (const float4*)(pm + tid * XS);
        float* dr = dest + tid * XS;
        #pragma unroll
        for (int q = 0; q < 8; ++q) {
            float4 pv = pr[q];
            float4 mv = m4[q];
            mv.x = fmaxf(mv.x, pv.x); mv.y = fmaxf(mv.y, pv.y);
            mv.z = fmaxf(mv.z, pv.z); mv.w = fmaxf(mv.w, pv.w);
            const int o = q * 4;
            dr[o + 0] = lrelu(fmaf(sb[o + 0], mv.x, tb[o + 0]));
            dr[o + 1] = lrelu(fmaf(sb[o + 1], mv.y, tb[o + 1]));
            dr[o + 2] = lrelu(fmaf(sb[o + 2], mv.z, tb[o + 2]));
            dr[o + 3] = lrelu(fmaf(sb[o + 3], mv.w, tb[o + 3]));
        }
    }
    __syncthreads();
}

// ---------------------------------------------------------------------------
// Single-conv EdgeConv (third block). Per-thread running max kept in smem
// (rolled o1 index); leaky applied after max (monotonic, s>0).
// ---------------------------------------------------------------------------
__device__ void edge_single(const float* __restrict__ xsrc, float* __restrict__ dest,
                            const int* __restrict__ idx,
                            const float* __restrict__ Wg /*32x64*/,
                            const float* __restrict__ sb, const float* __restrict__ tb,
                            float* __restrict__ scr, int tid)
{
    float* Wa    = scr;            // 1024
    float* Wd    = scr + 1024;     // 1024
    float* sbase = scr + 2048;     // 6600
    float* tm    = scr + 8648;     // 6600
    for (int i = tid; i < 1024; i += NTHR) {
        int o = i >> 5, c = i & 31;
        float wa = Wg[o * 64 + c];
        Wa[i] = wa;
        Wd[i] = Wg[o * 64 + 32 + c] - wa;
    }
    __syncthreads();
    if (tid < 2 * NPT) {
        const int n = tid % NPT;
        const int kh = tid / NPT;
        float4 ctr[8];
        const float4* cr = (const float4*)(xsrc + n * XS);
        #pragma unroll
        for (int q = 0; q < 8; ++q) ctr[q] = cr[q];
        for (int o1 = 0; o1 < 32; ++o1) {
            const float4* wd = (const float4*)(Wd + o1 * 32);
            float acc = 0.f;
            #pragma unroll
            for (int q = 0; q < 8; ++q) acc += dot4(wd[q], ctr[q]);
            sbase[tid * 33 + o1] = acc;
            tm[tid * 33 + o1] = -3.4e38f;
        }
        for (int kk = 0; kk < 5; ++kk) {
            const int j = idx[n * KNN + kh * 5 + kk];
            float4 nb[8];
            const float4* nr = (const float4*)(xsrc + j * XS);
            #pragma unroll
            for (int q = 0; q < 8; ++q) nb[q] = nr[q];
            for (int o1 = 0; o1 < 32; ++o1) {
                const float4* wa = (const float4*)(Wa + o1 * 32);
                float acc = sbase[tid * 33 + o1];
                #pragma unroll
                for (int q = 0; q < 8; ++q) acc += dot4(wa[q], nb[q]);
                tm[tid * 33 + o1] = fmaxf(tm[tid * 33 + o1], acc);
            }
        }
    }
    __syncthreads();
    if (tid < NPT) {
        for (int o = 0; o < 32; ++o) {
            float mv = fmaxf(tm[tid * 33 + o], tm[(tid + NPT) * 33 + o]);
            dest[tid * XS + o] = lrelu(fmaf(sb[o], mv, tb[o]));
        }
    }
    __syncthreads();
}

// ---------------------------------------------------------------------------
// Main fused kernel: one CTA per batch element.
// ---------------------------------------------------------------------------
extern "C" __global__ void __launch_bounds__(NTHR, 1)
dgcnn_fused(Ptrs P, float* __restrict__ out)
{
    extern __shared__ float sm[];
    float* x_cur = sm;              // 3600   (x0; later reused as y8)
    float* x1    = sm + 3600;       // 3600
    float* x2    = sm + 7200;       // 3600
    float* x3    = sm + 10800;      // 3600
    float* xx    = sm + 14400;      // 100
    int*   idx   = (int*)(sm + 14500); // 1000
    float* gbuf  = sm + 15500;      // 512
    float* pbuf  = sm + 16012;      // 128
    float* sts   = sm + 16140;      // 1728 scales/shifts
    float* scr   = sm + 17868;      // 17408 scratch (stage-dependent)

    const int tid = threadIdx.x;
    const int b = blockIdx.x;

    // load scales/shifts: s_i@64i, t_i@64i+32 (i<6); s6@384(512) t6@896 s7@1408 t7@1536 s8@1664 t8@1696
    for (int i = tid; i < 32 * 12; i += NTHR) {
        int g = i >> 5, c = i & 31;
        int si = g >> 1;
        sts[i] = (g & 1) ? P.t[si][c] : P.s[si][c];
    }
    for (int i = tid; i < 512; i += NTHR) { sts[384 + i] = P.s[6][i]; sts[896 + i] = P.t[6][i]; }
    for (int i = tid; i < 128; i += NTHR) { sts[1408 + i] = P.s[7][i]; sts[1536 + i] = P.t[7][i]; }
    for (int i = tid; i < 32; i += NTHR)  { sts[1664 + i] = P.s[8][i]; sts[1696 + i] = P.t[8][i]; }

    // ---- stage 0: load obs slice + W0, compute x0 = lrelu(s0*(W0 @ xr)+t0) ----
    for (int i = tid; i < 3000; i += NTHR) scr[i] = P.obs[b * 3000 + i];
    for (int i = tid; i < 960; i += NTHR)  scr[3000 + i] = P.W0[i];
    __syncthreads();
    for (int tt = tid; tt < 32 * NPT; tt += NTHR) {
        const int o = tt & 31, n = tt >> 5;
        const float* wr = scr + 3000 + o * 30;
        const float* xr = scr + n * 30;
        float acc = 0.f;
        #pragma unroll
        for (int c = 0; c < 30; ++c) acc = fmaf(wr[c], xr[c], acc);
        x_cur[n * XS + o] = lrelu(fmaf(sts[o], acc, sts[32 + o]));
    }
    __syncthreads();

    // ---- 3x (kNN + EdgeConv) ----
    knn_stage(x_cur, xx, idx, tid);
    edge_dual(x_cur, x1, idx, P.W1, P.W2, sts + 64, sts + 96, sts + 128, sts + 160, scr, tid);
    knn_stage(x1, xx, idx, tid);
    edge_dual(x1, x2, idx, P.W3, P.W4, sts + 192, sts + 224, sts + 256, sts + 288, scr, tid);
    knn_stage(x2, xx, idx, tid);
    edge_single(x2, x3, idx, P.W5, sts + 320, sts + 352, scr, tid);

    // ---- W6 (512x96) + global max over n -> g[512] (leaky after max; s6>0) ----
    #pragma unroll 1
    for (int rep = 0; rep < 2; ++rep) {
        const int o = tid + rep * NTHR;
        const float4* wr = (const float4*)(P.W6 + o * 96);
        float4 w[24];
        #pragma unroll
        for (int q = 0; q < 24; ++q) w[q] = __ldg(wr + q);
        float gmax = -3.4e38f;
        for (int n = 0; n < NPT; ++n) {
            const float4* a = (const float4*)(x1 + n * XS);
            const float4* bb = (const float4*)(x2 + n * XS);
            const float4* cc = (const float4*)(x3 + n * XS);
            float acc = 0.f;
            #pragma unroll
            for (int q = 0; q < 8; ++q) acc += dot4(w[q], a[q]);
            #pragma unroll
            for (int q = 0; q < 8; ++q) acc += dot4(w[8 + q], bb[q]);
            #pragma unroll
            for (int q = 0; q < 8; ++q) acc += dot4(w[16 + q], cc[q]);
            gmax = fmaxf(gmax, acc);
        }
        gbuf[o] = lrelu(fmaf(sts[384 + o], gmax, sts[896 + o]));
    }
    __syncthreads();

    // ---- p[o] = W7[o, :512] . g   (n-invariant part of h=concat[g,x1,x2,x3]) ----
    if (tid < 128) {
        const float4* wr = (const float4*)(P.W7 + tid * 608);
        const float4* gv = (const float4*)gbuf;
        float acc = 0.f;
        #pragma unroll 8
        for (int c4 = 0; c4 < 128; ++c4) acc += dot4(__ldg(wr + c4), gv[c4]);
        pbuf[tid] = acc;
    }
    __syncthreads();

    // ---- h2[n][o] = lrelu(s7*(p[o] + W7[o,512:608].xc[n]) + t7), o<128 ----
    {
        const int o = tid & 127, nh = tid >> 7;
        const float4* wr = (const float4*)(P.W7 + o * 608 + 512);
        float4 w[24];
        #pragma unroll
        for (int q = 0; q < 24; ++q) w[q] = __ldg(wr + q);
        const float po = pbuf[o], so = sts[1408 + o], to = sts[1536 + o];
        float* h2 = scr;  // 100 x 132
        for (int n = nh * 50; n < nh * 50 + 50; ++n) {
            const float4* a = (const float4*)(x1 + n * XS);
            const float4* bb = (const float4*)(x2 + n * XS);
            const float4* cc = (const float4*)(x3 + n * XS);
            float acc = po;
            #pragma unroll
            for (int q = 0; q < 8; ++q) acc += dot4(w[q], a[q]);
            #pragma unroll
            for (int q = 0; q < 8; ++q) acc += dot4(w[8 + q], bb[q]);
            #pragma unroll
            for (int q = 0; q < 8; ++q) acc += dot4(w[16 + q], cc[q]);
            h2[n * 132 + o] = lrelu(fmaf(so, acc, to));
        }
    }
    __syncthreads();

    // ---- W8 (32x128): y8[n][o2] = lrelu(s8*(W8.h2[n]) + t8) ----
    {
        const float* h2 = scr;
        float* y8 = x_cur;  // reuse
        for (int tt = tid; tt < 32 * NPT; tt += NTHR) {
            const int o2 = tt & 31, n = tt >> 5;
            const float4* wr = (const float4*)(P.W8 + o2 * 128);
            const float4* hr = (const float4*)(h2 + n * 132);
            float acc = 0.f;
            #pragma unroll
            for (int c4 = 0; c4 < 32; ++c4) acc += dot4(__ldg(wr + c4), hr[c4]);
            y8[n * XS + o2] = lrelu(fmaf(sts[1664 + o2], acc, sts[1696 + o2]));
        }
    }
    __syncthreads();

    // ---- final head: out[n] = W9 . y8[n] ----
    if (tid < NPT) {
        const float4* wr = (const float4*)P.W9;
        const float4* yr = (const float4*)(x_cur + tid * XS);
        float acc = 0.f;
        #pragma unroll
        for (int q = 0; q < 8; ++q) acc += dot4(__ldg(wr + q), yr[q]);
        out[b * NPT + tid] = acc;
    }
}

extern "C" void kernel_launch(void* const* d_in, const int* in_sizes, int n_in,
                              void* d_out, int out_size)
{
    Ptrs P;
    P.obs = (const float*)d_in[0];
    P.W0 = (const float*)d_in[1];  P.W1 = (const float*)d_in[2];
    P.W2 = (const float*)d_in[3];  P.W3 = (const float*)d_in[4];
    P.W4 = (const float*)d_in[5];  P.W5 = (const float*)d_in[6];
    P.W6 = (const float*)d_in[7];  P.W7 = (const float*)d_in[8];
    P.W8 = (const float*)d_in[9];  P.W9 = (const float*)d_in[10];

    // scale/shift ordering: dict-insertion (s0,t0,s1,t1,...) vs separated (s0..s8,t0..t8)
    const bool separated = (n_in > 17 && in_sizes[17] == 512);
    for (int i = 0; i < 9; ++i) {
        if (separated) {
            P.s[i] = (const float*)d_in[11 + i];
            P.t[i] = (const float*)d_in[20 + i];
        } else {
            P.s[i] = (const float*)d_in[11 + 2 * i];
            P.t[i] = (const float*)d_in[12 + 2 * i];
        }
    }

    const int B = in_sizes[0] / 3000;
    const int smem_bytes = 35276 * 4;  // ~137.8 KB
    cudaFuncSetAttribute(dgcnn_fused, cudaFuncAttributeMaxDynamicSharedMemorySize, smem_bytes);
    dgcnn_fused<<<B, NTHR, smem_bytes>>>(P, (float*)d_out);
}

// round 2
// speedup vs baseline: 1.1425x; 1.1425x over previous
#include <cuda_runtime.h>

#define NPT   100
#define KNN   10
#define XS    36    // padded row stride (floats), 144B = 16B aligned
#define NTHR  512

typedef unsigned long long u64;

struct Ptrs {
    const float* obs;
    const float* W0; const float* W1; const float* W2; const float* W3; const float* W4;
    const float* W5; const float* W6; const float* W7; const float* W8; const float* W9;
    const float* s[9]; const float* t[9];
};

__device__ __forceinline__ float lrelu(float v) { return fmaxf(v, 0.2f * v); }

// ---- packed fp32x2 helpers (FFMA2: only reachable via PTX) ----
__device__ __forceinline__ u64 pack2(float lo, float hi) {
    u64 r; asm("mov.b64 %0,{%1,%2};" : "=l"(r) : "f"(lo), "f"(hi)); return r;
}
__device__ __forceinline__ void fma2(u64& d, u64 a, u64 b) {
    asm("fma.rn.f32x2 %0,%1,%2,%0;" : "+l"(d) : "l"(a), "l"(b));
}
__device__ __forceinline__ u64 add2(u64 a, u64 b) {
    u64 r; asm("add.rn.f32x2 %0,%1,%2;" : "=l"(r) : "l"(a), "l"(b)); return r;
}
__device__ __forceinline__ void unpack2(u64 v, float& a, float& b) {
    asm("mov.b64 {%0,%1},%2;" : "=f"(a), "=f"(b) : "l"(v));
}
__device__ __forceinline__ float hsum(u64 v) { float a, b; unpack2(v, a, b); return a + b; }

// load a 32-float row (16B aligned) into 16 packed u64 registers
__device__ __forceinline__ void ldrow(u64* r, const float* p) {
    const ulonglong2* q = (const ulonglong2*)p;
    #pragma unroll
    for (int i = 0; i < 8; ++i) { ulonglong2 v = q[i]; r[2*i] = v.x; r[2*i+1] = v.y; }
}
// 32-elem dot: a in regs (16 u64), b a 16B-aligned smem row
__device__ __forceinline__ float dot32s(const u64* a, const float* b) {
    const ulonglong2* q = (const ulonglong2*)b;
    u64 s0 = 0, s1 = 0;
    #pragma unroll
    for (int i = 0; i < 8; ++i) { ulonglong2 v = q[i]; fma2(s0, a[2*i], v.x); fma2(s1, a[2*i+1], v.y); }
    return hsum(add2(s0, s1));
}

// ---------------------------------------------------------------------------
// kNN: 200 threads scan j-halves of 50, write per-half top-10; 100 threads
// merge (stable, lower index wins ties -> matches jax.lax.top_k).
// ---------------------------------------------------------------------------
__device__ void knn_stage(const float* __restrict__ xsrc, float* __restrict__ xx,
                          int* __restrict__ idx, float* __restrict__ scr, int tid)
{
    if (tid < NPT) {
        u64 xi[16]; ldrow(xi, xsrc + tid * XS);
        xx[tid] = dot32s(xi, xsrc + tid * XS);
    }
    __syncthreads();
    float* vbuf = scr;                    // 200*10
    int*   ibuf = (int*)(scr + 2048);     // 200*10
    if (tid < 2 * NPT) {
        const int n = tid % NPT, h = tid / NPT;
        u64 xi[16]; ldrow(xi, xsrc + n * XS);
        const float nxi = xx[n];
        float v[KNN]; int id[KNN];
        #pragma unroll
        for (int p = 0; p < KNN; ++p) { v[p] = -3.4e38f; id[p] = 0; }
        for (int j = h * 50; j < h * 50 + 50; ++j) {
            float d = 2.f * dot32s(xi, xsrc + j * XS) - nxi - xx[j];
            if (d > v[KNN - 1]) {
                float dv = d; int di = j;
                #pragma unroll
                for (int p = 0; p < KNN; ++p) {
                    if (dv > v[p]) {
                        float tv = v[p]; int ti = id[p];
                        v[p] = dv; id[p] = di; dv = tv; di = ti;
                    }
                }
            }
        }
        #pragma unroll
        for (int p = 0; p < KNN; ++p) { vbuf[tid * KNN + p] = v[p]; ibuf[tid * KNN + p] = id[p]; }
    }
    __syncthreads();
    if (tid < NPT) {
        const float* va = vbuf + tid * KNN; const float* vb = vbuf + (tid + NPT) * KNN;
        const int*   ia = ibuf + tid * KNN; const int*   ib = ibuf + (tid + NPT) * KNN;
        int pa = 0, pb = 0;
        #pragma unroll
        for (int p = 0; p < KNN; ++p) {
            bool ta = va[pa] >= vb[pb];        // half0 has lower j: wins ties
            idx[tid * KNN + p] = ta ? ia[pa] : ib[pb];
            if (ta) ++pa; else ++pb;
        }
    }
    __syncthreads();
}

// ---------------------------------------------------------------------------
// Dual-conv EdgeConv. 400 threads = (n, kg of 4 groups: 3/3/2/2 neighbors).
// y1 = lrelu(sa*(Wa.nbr + Wd.ctr)+ta); z = Wbt.y1; partial max in smem tm;
// final 4-way combine + second BN/lrelu.
// ---------------------------------------------------------------------------
__device__ void edge_dual(const float* __restrict__ xsrc, float* __restrict__ dest,
                          const int* __restrict__ idx,
                          const float* __restrict__ Wg, const float* __restrict__ Wbg,
                          const float* __restrict__ sa, const float* __restrict__ ta,
                          const float* __restrict__ sb, const float* __restrict__ tb,
                          float* __restrict__ scr, int tid)
{
    float* Wa    = scr;             // 1024
    float* Wd    = scr + 1024;      // 1024  (W[:,32:]-W[:,:32])
    float* Wbt   = scr + 2048;      // 1024  transposed
    float* sbase = scr + 3072;      // 400*33 = 13200
    float* tm    = scr + 16272;     // 400*33 = 13200
    for (int i = tid; i < 1024; i += NTHR) {
        int o = i >> 5, c = i & 31;
        float wa = Wg[o * 64 + c];
        Wa[i] = wa;
        Wd[i] = Wg[o * 64 + 32 + c] - wa;
        Wbt[c * 32 + o] = Wbg[i];
    }
    __syncthreads();
    if (tid < 4 * NPT) {
        const int n = tid % NPT, kg = tid / NPT;
        const int k0 = (kg < 2) ? kg * 3 : 6 + (kg - 2) * 2;
        const int nk = (kg < 2) ? 3 : 2;
        {
            u64 ctr[16]; ldrow(ctr, xsrc + n * XS);
            for (int o1 = 0; o1 < 32; ++o1) {
                sbase[tid * 33 + o1] = dot32s(ctr, Wd + o1 * 32);
                tm[tid * 33 + o1] = -3.4e38f;
            }
        }
        for (int kk = 0; kk < nk; ++kk) {
            const int j = idx[n * KNN + k0 + kk];
            u64 nb[16]; ldrow(nb, xsrc + j * XS);
            u64 z[16];
            #pragma unroll
            for (int i = 0; i < 16; ++i) z[i] = 0;
            for (int o1 = 0; o1 < 32; ++o1) {
                u64 s0 = 0, s1 = 0;
                const ulonglong2* wa2 = (const ulonglong2*)(Wa + o1 * 32);
                #pragma unroll
                for (int i = 0; i < 8; ++i) { ulonglong2 w = wa2[i]; fma2(s0, nb[2*i], w.x); fma2(s1, nb[2*i+1], w.y); }
                const float acc = sbase[tid * 33 + o1] + hsum(add2(s0, s1));
                const float y1 = lrelu(fmaf(sa[o1], acc, ta[o1]));
                const u64 y2 = pack2(y1, y1);
                const ulonglong2* wb2 = (const ulonglong2*)(Wbt + o1 * 32);
                #pragma unroll
                for (int i = 0; i < 8; ++i) { ulonglong2 w = wb2[i]; fma2(z[2*i], y2, w.x); fma2(z[2*i+1], y2, w.y); }
            }
            #pragma unroll
            for (int i = 0; i < 16; ++i) {
                float a, b; unpack2(z[i], a, b);
                tm[tid * 33 + 2*i]     = fmaxf(tm[tid * 33 + 2*i], a);
                tm[tid * 33 + 2*i + 1] = fmaxf(tm[tid * 33 + 2*i + 1], b);
            }
        }
    }
    __syncthreads();
    for (int i = tid; i < 32 * NPT; i += NTHR) {
        const int n = i >> 5, o = i & 31;
        float m = tm[n * 33 + o];
        m = fmaxf(m, tm[(NPT + n) * 33 + o]);
        m = fmaxf(m, tm[(2 * NPT + n) * 33 + o]);
        m = fmaxf(m, tm[(3 * NPT + n) * 33 + o]);
        dest[n * XS + o] = lrelu(fmaf(sb[o], m, tb[o]));
    }
    __syncthreads();
}

// ---------------------------------------------------------------------------
// Single-conv EdgeConv (third block). 400 threads, neighbors padded to 3
// (duplicate is harmless under max). Wa row register-cached per o1.
// ---------------------------------------------------------------------------
__device__ void edge_single(const float* __restrict__ xsrc, float* __restrict__ dest,
                            const int* __restrict__ idx,
                            const float* __restrict__ Wg,
                            const float* __restrict__ sb, const float* __restrict__ tb,
                            float* __restrict__ scr, int tid)
{
    float* Wa    = scr;             // 1024
    float* Wd    = scr + 1024;      // 1024
    float* sbase = scr + 3072;      // 13200
    float* tm    = scr + 16272;     // 13200
    for (int i = tid; i < 1024; i += NTHR) {
        int o = i >> 5, c = i & 31;
        float wa = Wg[o * 64 + c];
        Wa[i] = wa;
        Wd[i] = Wg[o * 64 + 32 + c] - wa;
    }
    __syncthreads();
    if (tid < 4 * NPT) {
        const int n = tid % NPT, kg = tid / NPT;
        const int k0 = (kg < 2) ? kg * 3 : 6 + (kg - 2) * 2;
        const int nk = (kg < 2) ? 3 : 2;
        {
            u64 ctr[16]; ldrow(ctr, xsrc + n * XS);
            for (int o1 = 0; o1 < 32; ++o1)
                sbase[tid * 33 + o1] = dot32s(ctr, Wd + o1 * 32);
        }
        u64 nb[3][16];
        ldrow(nb[0], xsrc + idx[n * KNN + k0] * XS);
        ldrow(nb[1], xsrc + idx[n * KNN + k0 + 1] * XS);
        ldrow(nb[2], xsrc + idx[n * KNN + k0 + ((nk > 2) ? 2 : 1)] * XS);
        for (int o1 = 0; o1 < 32; ++o1) {
            const ulonglong2* wa2 = (const ulonglong2*)(Wa + o1 * 32);
            u64 a0 = 0, a1 = 0, b0 = 0, b1 = 0, c0 = 0, c1 = 0;
            #pragma unroll
            for (int i = 0; i < 8; ++i) {
                ulonglong2 w = wa2[i];
                fma2(a0, nb[0][2*i], w.x); fma2(a1, nb[0][2*i+1], w.y);
                fma2(b0, nb[1][2*i], w.x); fma2(b1, nb[1][2*i+1], w.y);
                fma2(c0, nb[2][2*i], w.x); fma2(c1, nb[2][2*i+1], w.y);
            }
            float m = fmaxf(fmaxf(hsum(add2(a0, a1)), hsum(add2(b0, b1))), hsum(add2(c0, c1)));
            tm[tid * 33 + o1] = sbase[tid * 33 + o1] + m;
        }
    }
    __syncthreads();
    for (int i = tid; i < 32 * NPT; i += NTHR) {
        const int n = i >> 5, o = i & 31;
        float m = tm[n * 33 + o];
        m = fmaxf(m, tm[(NPT + n) * 33 + o]);
        m = fmaxf(m, tm[(2 * NPT + n) * 33 + o]);
        m = fmaxf(m, tm[(3 * NPT + n) * 33 + o]);
        dest[n * XS + o] = lrelu(fmaf(sb[o], m, tb[o]));
    }
    __syncthreads();
}

// ---------------------------------------------------------------------------
// Main fused kernel: one CTA per batch element, 512 threads.
// ---------------------------------------------------------------------------
extern "C" __global__ void __launch_bounds__(NTHR, 1)
dgcnn_fused(Ptrs P, float* __restrict__ out)
{
    extern __shared__ float sm[];
    float* x_cur = sm;                   // 3600 (x0; later y8)
    float* x1    = sm + 3600;
    float* x2    = sm + 7200;
    float* x3    = sm + 10800;
    float* xx    = sm + 14400;           // 128
    int*   idx   = (int*)(sm + 14528);   // 1000
    float* gbuf  = sm + 15528;           // 512
    float* pbuf  = sm + 16040;           // 128
    float* sts   = sm + 16168;           // 1728
    float* scr   = sm + 17896;           // 29472 scratch

    const int tid = threadIdx.x;
    const int b = blockIdx.x;

    for (int i = tid; i < 32 * 12; i += NTHR) {
        int g = i >> 5, c = i & 31, si = g >> 1;
        sts[i] = (g & 1) ? P.t[si][c] : P.s[si][c];
    }
    for (int i = tid; i < 512; i += NTHR) { sts[384 + i] = P.s[6][i]; sts[896 + i] = P.t[6][i]; }
    for (int i = tid; i < 128; i += NTHR) { sts[1408 + i] = P.s[7][i]; sts[1536 + i] = P.t[7][i]; }
    for (int i = tid; i < 32; i += NTHR)  { sts[1664 + i] = P.s[8][i]; sts[1696 + i] = P.t[8][i]; }

    // ---- stage 0 ----
    for (int i = tid; i < 3000; i += NTHR) scr[i] = P.obs[b * 3000 + i];
    for (int i = tid; i < 960; i += NTHR)  scr[3000 + i] = P.W0[i];
    __syncthreads();
    for (int tt = tid; tt < 32 * NPT; tt += NTHR) {
        const int o = tt & 31, n = tt >> 5;
        const u64* wr = (const u64*)(scr + 3000 + o * 30);   // 8B aligned (o*120B)
        const u64* xr = (const u64*)(scr + n * 30);
        u64 s0 = 0, s1 = 0;
        #pragma unroll
        for (int i = 0; i < 14; i += 2) { fma2(s0, wr[i], xr[i]); fma2(s1, wr[i+1], xr[i+1]); }
        fma2(s0, wr[14], xr[14]);
        const float acc = hsum(add2(s0, s1));
        x_cur[n * XS + o] = lrelu(fmaf(sts[o], acc, sts[32 + o]));
    }
    __syncthreads();

    // ---- 3x (kNN + EdgeConv) ----
    knn_stage(x_cur, xx, idx, scr, tid);
    edge_dual(x_cur, x1, idx, P.W1, P.W2, sts + 64, sts + 96, sts + 128, sts + 160, scr, tid);
    knn_stage(x1, xx, idx, scr, tid);
    edge_dual(x1, x2, idx, P.W3, P.W4, sts + 192, sts + 224, sts + 256, sts + 288, scr, tid);
    knn_stage(x2, xx, idx, scr, tid);
    edge_single(x2, x3, idx, P.W5, sts + 320, sts + 352, scr, tid);

    // ---- W6 (512x96) + global max -> g[512]; one output per thread ----
    {
        const int o = tid;
        u64 w[48];
        const ulonglong2* wr = (const ulonglong2*)(P.W6 + o * 96);
        #pragma unroll
        for (int q = 0; q < 24; ++q) { ulonglong2 v = __ldg(wr + q); w[2*q] = v.x; w[2*q+1] = v.y; }
        float gmax = -3.4e38f;
        for (int n = 0; n < NPT; ++n) {
            u64 s0 = 0, s1 = 0;
            const ulonglong2* a = (const ulonglong2*)(x1 + n * XS);
            const ulonglong2* bb = (const ulonglong2*)(x2 + n * XS);
            const ulonglong2* cc = (const ulonglong2*)(x3 + n * XS);
            #pragma unroll
            for (int i = 0; i < 8; ++i) { ulonglong2 v = a[i];  fma2(s0, w[2*i],      v.x); fma2(s1, w[2*i+1],      v.y); }
            #pragma unroll
            for (int i = 0; i < 8; ++i) { ulonglong2 v = bb[i]; fma2(s0, w[16+2*i],   v.x); fma2(s1, w[16+2*i+1],   v.y); }
            #pragma unroll
            for (int i = 0; i < 8; ++i) { ulonglong2 v = cc[i]; fma2(s0, w[32+2*i],   v.x); fma2(s1, w[32+2*i+1],   v.y); }
            gmax = fmaxf(gmax, hsum(add2(s0, s1)));
        }
        gbuf[o] = lrelu(fmaf(sts[384 + o], gmax, sts[896 + o]));
    }
    __syncthreads();

    // ---- p[o] = W7[o,:512] . g ----
    if (tid < 128) {
        const ulonglong2* wr = (const ulonglong2*)(P.W7 + tid * 608);
        const ulonglong2* gv = (const ulonglong2*)gbuf;
        u64 s0 = 0, s1 = 0;
        #pragma unroll 16
        for (int q = 0; q < 128; ++q) {
            ulonglong2 wv = __ldg(wr + q); ulonglong2 g = gv[q];
            fma2(s0, wv.x, g.x); fma2(s1, wv.y, g.y);
        }
        pbuf[tid] = hsum(add2(s0, s1));
    }
    __syncthreads();

    // ---- h2 + staged W8 copy ----
    {
        float* w8p = scr + 13216;  // 32 rows x 132 padded
        for (int i = tid; i < 4096; i += NTHR) {
            int o2 = i >> 7, c = i & 127;
            w8p[o2 * 132 + c] = P.W8[i];
        }
        const int o = tid & 127, nh = tid >> 7;
        u64 w[48];
        const ulonglong2* wr = (const ulonglong2*)(P.W7 + o * 608 + 512);
        #pragma unroll
        for (int q = 0; q < 24; ++q) { ulonglong2 v = __ldg(wr + q); w[2*q] = v.x; w[2*q+1] = v.y; }
        const float po = pbuf[o], so = sts[1408 + o], to = sts[1536 + o];
        float* h2 = scr;  // 100 x 132
        for (int n = nh * 25; n < nh * 25 + 25; ++n) {
            u64 s0 = 0, s1 = 0;
            const ulonglong2* a = (const ulonglong2*)(x1 + n * XS);
            const ulonglong2* bb = (const ulonglong2*)(x2 + n * XS);
            const ulonglong2* cc = (const ulonglong2*)(x3 + n * XS);
            #pragma unroll
            for (int i = 0; i < 8; ++i) { ulonglong2 v = a[i];  fma2(s0, w[2*i],    v.x); fma2(s1, w[2*i+1],    v.y); }
            #pragma unroll
            for (int i = 0; i < 8; ++i) { ulonglong2 v = bb[i]; fma2(s0, w[16+2*i], v.x); fma2(s1, w[16+2*i+1], v.y); }
            #pragma unroll
            for (int i = 0; i < 8; ++i) { ulonglong2 v = cc[i]; fma2(s0, w[32+2*i], v.x); fma2(s1, w[32+2*i+1], v.y); }
            const float acc = po + hsum(add2(s0, s1));
            h2[n * 132 + o] = lrelu(fmaf(so, acc, to));
        }
    }
    __syncthreads();

    // ---- W8 (32x128): per warp one n, lanes = o2; weights padded in smem ----
    {
        const float* h2 = scr;
        const float* w8p = scr + 13216;
        float* y8 = x_cur;
        for (int tt = tid; tt < 32 * NPT; tt += NTHR) {
            const int o2 = tt & 31, n = tt >> 5;
            const ulonglong2* wr = (const ulonglong2*)(w8p + o2 * 132);
            const ulonglong2* hr = (const ulonglong2*)(h2 + n * 132);
            u64 s0 = 0, s1 = 0;
            #pragma unroll
            for (int q = 0; q < 32; ++q) {
                ulonglong2 wv = wr[q]; ulonglong2 hv = hr[q];
                fma2(s0, wv.x, hv.x); fma2(s1, wv.y, hv.y);
            }
            y8[n * XS + o2] = lrelu(fmaf(sts[1664 + o2], hsum(add2(s0, s1)), sts[1696 + o2]));
        }
    }
    __syncthreads();

    // ---- final head ----
    if (tid < NPT) {
        u64 w[16];
        const ulonglong2* wr = (const ulonglong2*)P.W9;
        #pragma unroll
        for (int q = 0; q < 8; ++q) { ulonglong2 v = __ldg(wr + q); w[2*q] = v.x; w[2*q+1] = v.y; }
        out[b * NPT + tid] = dot32s(w, x_cur + tid * XS);
    }
}

extern "C" void kernel_launch(void* const* d_in, const int* in_sizes, int n_in,
                              void* d_out, int out_size)
{
    Ptrs P;
    P.obs = (const float*)d_in[0];
    P.W0 = (const float*)d_in[1];  P.W1 = (const float*)d_in[2];
    P.W2 = (const float*)d_in[3];  P.W3 = (const float*)d_in[4];
    P.W4 = (const float*)d_in[5];  P.W5 = (const float*)d_in[6];
    P.W6 = (const float*)d_in[7];  P.W7 = (const float*)d_in[8];
    P.W8 = (const float*)d_in[9];  P.W9 = (const float*)d_in[10];

    const bool separated = (n_in > 17 && in_sizes[17] == 512);
    for (int i = 0; i < 9; ++i) {
        if (separated) {
            P.s[i] = (const float*)d_in[11 + i];
            P.t[i] = (const float*)d_in[20 + i];
        } else {
            P.s[i] = (const float*)d_in[11 + 2 * i];
            P.t[i] = (const float*)d_in[12 + 2 * i];
        }
    }

    const int B = in_sizes[0] / 3000;
    const int smem_bytes = 47368 * 4;  // ~185 KB
    cudaFuncSetAttribute(dgcnn_fused, cudaFuncAttributeMaxDynamicSharedMemorySize, smem_bytes);
    dgcnn_fused<<<B, NTHR, smem_bytes>>>(P, (float*)d_out);
}

// round 4
// speedup vs baseline: 1.2833x; 1.1232x over previous
#include <cuda_runtime.h>

#define NPT   100
#define KNN   10
#define XS    36
#define NTHR  256

typedef unsigned long long u64;

struct Ptrs {
    const float* obs;
    const float* W0; const float* W1; const float* W2; const float* W3; const float* W4;
    const float* W5; const float* W6; const float* W7; const float* W8; const float* W9;
    const float* s[9]; const float* t[9];
};

__device__ __forceinline__ float lrelu(float v) { return fmaxf(v, 0.2f * v); }

__device__ __forceinline__ u64 pack2(float lo, float hi) {
    u64 r; asm("mov.b64 %0,{%1,%2};" : "=l"(r) : "f"(lo), "f"(hi)); return r;
}
__device__ __forceinline__ void fma2(u64& d, u64 a, u64 b) {
    asm("fma.rn.f32x2 %0,%1,%2,%0;" : "+l"(d) : "l"(a), "l"(b));
}
__device__ __forceinline__ u64 add2(u64 a, u64 b) {
    u64 r; asm("add.rn.f32x2 %0,%1,%2;" : "=l"(r) : "l"(a), "l"(b)); return r;
}
__device__ __forceinline__ void unpack2(u64 v, float& a, float& b) {
    asm("mov.b64 {%0,%1},%2;" : "=f"(a), "=f"(b) : "l"(v));
}
__device__ __forceinline__ float hsum(u64 v) { float a, b; unpack2(v, a, b); return a + b; }

__device__ __forceinline__ void ldrow(u64* r, const float* p) {
    const ulonglong2* q = (const ulonglong2*)p;
    #pragma unroll
    for (int i = 0; i < 8; ++i) { ulonglong2 v = q[i]; r[2*i] = v.x; r[2*i+1] = v.y; }
}
__device__ __forceinline__ float dot32s(const u64* a, const float* b) {
    const ulonglong2* q = (const ulonglong2*)b;
    u64 s0 = 0, s1 = 0;
    #pragma unroll
    for (int i = 0; i < 8; ++i) { ulonglong2 v = q[i]; fma2(s0, a[2*i], v.x); fma2(s1, a[2*i+1], v.y); }
    return hsum(add2(s0, s1));
}
// dot of two 16B-aligned smem rows (no register staging of either)
__device__ __forceinline__ float dot32ss(const float* a, const float* b) {
    const ulonglong2* pa = (const ulonglong2*)a;
    const ulonglong2* pb = (const ulonglong2*)b;
    u64 s0 = 0, s1 = 0;
    #pragma unroll
    for (int i = 0; i < 8; ++i) {
        ulonglong2 va = pa[i], vb = pb[i];
        fma2(s0, va.x, vb.x); fma2(s1, va.y, vb.y);
    }
    return hsum(add2(s0, s1));
}

// ---------------------------------------------------------------------------
// kNN: 200 threads scan j-halves of 50 -> per-half top-10; 100 threads merge.
// ---------------------------------------------------------------------------
__device__ void knn_stage(const float* __restrict__ xsrc, float* __restrict__ xx,
                          int* __restrict__ idx, float* __restrict__ scr, int tid)
{
    if (tid < NPT) {
        xx[tid] = dot32ss(xsrc + tid * XS, xsrc + tid * XS);
    }
    __syncthreads();
    float* vbuf = scr;                    // 200*10
    int*   ibuf = (int*)(scr + 2048);     // 200*10
    if (tid < 2 * NPT) {
        const int n = tid % NPT, h = tid / NPT;
        u64 xi[16]; ldrow(xi, xsrc + n * XS);
        const float nxi = xx[n];
        float v[KNN]; int id[KNN];
        #pragma unroll
        for (int p = 0; p < KNN; ++p) { v[p] = -3.4e38f; id[p] = 0; }
        for (int j = h * 50; j < h * 50 + 50; ++j) {
            float d = 2.f * dot32s(xi, xsrc + j * XS) - nxi - xx[j];
            if (d > v[KNN - 1]) {
                float dv = d; int di = j;
                #pragma unroll
                for (int p = 0; p < KNN; ++p) {
                    if (dv > v[p]) {
                        float tv = v[p]; int ti = id[p];
                        v[p] = dv; id[p] = di; dv = tv; di = ti;
                    }
                }
            }
        }
        #pragma unroll
        for (int p = 0; p < KNN; ++p) { vbuf[tid * KNN + p] = v[p]; ibuf[tid * KNN + p] = id[p]; }
    }
    __syncthreads();
    if (tid < NPT) {
        const float* va = vbuf + tid * KNN; const float* vb = vbuf + (tid + NPT) * KNN;
        const int*   ia = ibuf + tid * KNN; const int*   ib = ibuf + (tid + NPT) * KNN;
        int pa = 0, pb = 0;
        #pragma unroll
        for (int p = 0; p < KNN; ++p) {
            bool ta = va[pa] >= vb[pb];
            idx[tid * KNN + p] = ta ? ia[pa] : ib[pb];
            if (ta) ++pa; else ++pb;
        }
    }
    __syncthreads();
}

// ---------------------------------------------------------------------------
// Dual-conv EdgeConv, 200 active threads = (n, kh of 2 halves, 5 nbrs each).
// ---------------------------------------------------------------------------
__device__ void edge_dual(const float* __restrict__ xsrc, float* __restrict__ dest,
                          const int* __restrict__ idx,
                          const float* __restrict__ Wg, const float* __restrict__ Wbg,
                          const float* __restrict__ sa, const float* __restrict__ ta,
                          const float* __restrict__ sb, const float* __restrict__ tb,
                          float* __restrict__ scr,
                          float* __restrict__ pmA, float* __restrict__ pmB, int tid)
{
    float* Wa    = scr;             // 1024
    float* Wd    = scr + 1024;      // 1024
    float* Wbt   = scr + 2048;      // 1024
    float* sbase = scr + 3072;      // 200*33 = 6600
    for (int i = tid; i < 1024; i += NTHR) {
        int o = i >> 5, c = i & 31;
        float wa = Wg[o * 64 + c];
        Wa[i] = wa;
        Wd[i] = Wg[o * 64 + 32 + c] - wa;
        Wbt[c * 32 + o] = Wbg[i];
    }
    __syncthreads();
    if (tid < 2 * NPT) {
        const int n = tid % NPT, kh = tid / NPT;
        for (int o1 = 0; o1 < 32; ++o1)
            sbase[tid * 33 + o1] = dot32ss(Wd + o1 * 32, xsrc + n * XS);
        u64 m[16];
        #pragma unroll
        for (int i = 0; i < 16; ++i) m[i] = pack2(-3.4e38f, -3.4e38f);
        for (int kk = 0; kk < 5; ++kk) {
            const int j = idx[n * KNN + kh * 5 + kk];
            u64 nb[16]; ldrow(nb, xsrc + j * XS);
            u64 z[16];
            #pragma unroll
            for (int i = 0; i < 16; ++i) z[i] = 0;
            for (int o1 = 0; o1 < 32; ++o1) {
                u64 s0 = 0, s1 = 0;
                const ulonglong2* wa2 = (const ulonglong2*)(Wa + o1 * 32);
                #pragma unroll
                for (int i = 0; i < 8; ++i) { ulonglong2 w = wa2[i]; fma2(s0, nb[2*i], w.x); fma2(s1, nb[2*i+1], w.y); }
                const float acc = sbase[tid * 33 + o1] + hsum(add2(s0, s1));
                const float y1 = lrelu(fmaf(sa[o1], acc, ta[o1]));
                const u64 y2 = pack2(y1, y1);
                const ulonglong2* wb2 = (const ulonglong2*)(Wbt + o1 * 32);
                #pragma unroll
                for (int i = 0; i < 8; ++i) { ulonglong2 w = wb2[i]; fma2(z[2*i], y2, w.x); fma2(z[2*i+1], y2, w.y); }
            }
            #pragma unroll
            for (int i = 0; i < 16; ++i) {
                float za, zb, ma, mb;
                unpack2(z[i], za, zb); unpack2(m[i], ma, mb);
                m[i] = pack2(fmaxf(ma, za), fmaxf(mb, zb));
            }
        }
        float* pr = (kh == 0 ? pmA : pmB) + n * XS;
        #pragma unroll
        for (int i = 0; i < 16; ++i) {
            float a, b; unpack2(m[i], a, b);
            pr[2*i] = a; pr[2*i+1] = b;
        }
    }
    __syncthreads();
    for (int i = tid; i < 32 * NPT; i += NTHR) {
        const int n = i >> 5, o = i & 31;
        float mv = fmaxf(pmA[n * XS + o], pmB[n * XS + o]);
        dest[n * XS + o] = lrelu(fmaf(sb[o], mv, tb[o]));
    }
    __syncthreads();
}

// ---------------------------------------------------------------------------
// Single-conv EdgeConv (third block). 200 active threads, neighbors in pairs
// (last pair duplicates nbr 4 — harmless under max).
// ---------------------------------------------------------------------------
__device__ void edge_single(const float* __restrict__ xsrc, float* __restrict__ dest,
                            const int* __restrict__ idx,
                            const float* __restrict__ Wg,
                            const float* __restrict__ sb, const float* __restrict__ tb,
                            float* __restrict__ scr, float* __restrict__ sbase, int tid)
{
    float* Wa = scr;            // 1024
    float* Wd = scr + 1024;     // 1024
    float* tm = scr + 2048;     // 200*33 = 6600
    for (int i = tid; i < 1024; i += NTHR) {
        int o = i >> 5, c = i & 31;
        float wa = Wg[o * 64 + c];
        Wa[i] = wa;
        Wd[i] = Wg[o * 64 + 32 + c] - wa;
    }
    __syncthreads();
    if (tid < 2 * NPT) {
        const int n = tid % NPT, kh = tid / NPT;
        if (kh == 0) {
            for (int o1 = 0; o1 < 32; ++o1)
                sbase[n * 33 + o1] = dot32ss(Wd + o1 * 32, xsrc + n * XS);
        }
        for (int o1 = 0; o1 < 32; ++o1) tm[tid * 33 + o1] = -3.4e38f;
        #pragma unroll 1
        for (int g = 0; g < 3; ++g) {
            const int ka = g * 2, kb = (g == 2) ? 4 : g * 2 + 1;
            const int ja = idx[n * KNN + kh * 5 + ka];
            const int jb = idx[n * KNN + kh * 5 + kb];
            u64 na[16], nbv[16];
            ldrow(na, xsrc + ja * XS);
            ldrow(nbv, xsrc + jb * XS);
            for (int o1 = 0; o1 < 32; ++o1) {
                const ulonglong2* wa2 = (const ulonglong2*)(Wa + o1 * 32);
                u64 a0 = 0, a1 = 0, b0 = 0, b1 = 0;
                #pragma unroll
                for (int i = 0; i < 8; ++i) {
                    ulonglong2 w = wa2[i];
                    fma2(a0, na[2*i], w.x);  fma2(a1, na[2*i+1], w.y);
                    fma2(b0, nbv[2*i], w.x); fma2(b1, nbv[2*i+1], w.y);
                }
                float mv = fmaxf(hsum(add2(a0, a1)), hsum(add2(b0, b1)));
                tm[tid * 33 + o1] = fmaxf(tm[tid * 33 + o1], mv);
            }
        }
    }
    __syncthreads();
    for (int i = tid; i < 32 * NPT; i += NTHR) {
        const int n = i >> 5, o = i & 31;
        float mv = fmaxf(tm[n * 33 + o], tm[(NPT + n) * 33 + o]) + sbase[n * 33 + o];
        dest[n * XS + o] = lrelu(fmaf(sb[o], mv, tb[o]));
    }
    __syncthreads();
}

// ---------------------------------------------------------------------------
// Main fused kernel: one CTA per batch element, 256 threads, 2 CTAs/SM.
// smem map (floats): x0@0 x1@3600 x2@7200 x3@10800 | xx@14400 idx@14528(..15528)
// gbuf@15528 pbuf@16040 sts@16168 | scr@16552..26952   (NO overlaps)
// ---------------------------------------------------------------------------
extern "C" __global__ void __launch_bounds__(NTHR, 2)
dgcnn_fused(Ptrs P, float* __restrict__ out)
{
    extern __shared__ float sm[];
    float* x0   = sm;
    float* x1   = sm + 3600;
    float* x2   = sm + 7200;
    float* x3   = sm + 10800;
    float* xx   = sm + 14400;
    int*   idx  = (int*)(sm + 14528);   // ends 15528
    float* gbuf = sm + 15528;           // 512 -> 16040
    float* pbuf = sm + 16040;           // 128 -> 16168
    float* sts  = sm + 16168;           // 384 -> 16552
    float* scr  = sm + 16552;           // 10400 -> 26952

    const int tid = threadIdx.x;
    const int b = blockIdx.x;

    for (int i = tid; i < 32 * 12; i += NTHR) {
        int g = i >> 5, c = i & 31, si = g >> 1;
        sts[i] = (g & 1) ? P.t[si][c] : P.s[si][c];
    }

    // ---- stage 0: x0 = lrelu(s0*(W0 @ obs_rows)+t0) ----
    for (int i = tid; i < 3000; i += NTHR) scr[i] = P.obs[b * 3000 + i];
    for (int i = tid; i < 960; i += NTHR)  scr[3072 + i] = P.W0[i];
    __syncthreads();
    for (int tt = tid; tt < 32 * NPT; tt += NTHR) {
        const int o = tt & 31, n = tt >> 5;
        const u64* wr = (const u64*)(scr + 3072 + o * 30);
        const u64* xr = (const u64*)(scr + n * 30);
        u64 s0 = 0, s1 = 0;
        #pragma unroll
        for (int i = 0; i < 14; i += 2) { fma2(s0, wr[i], xr[i]); fma2(s1, wr[i+1], xr[i+1]); }
        fma2(s0, wr[14], xr[14]);
        x0[n * XS + o] = lrelu(fmaf(sts[o], hsum(add2(s0, s1)), sts[32 + o]));
    }
    __syncthreads();

    // ---- 3x (kNN + EdgeConv); pm buffers overlaid on dead tiles ----
    knn_stage(x0, xx, idx, scr, tid);
    edge_dual(x0, x1, idx, P.W1, P.W2, sts + 64, sts + 96, sts + 128, sts + 160,
              scr, x2, x3, tid);
    knn_stage(x1, xx, idx, scr, tid);
    edge_dual(x1, x2, idx, P.W3, P.W4, sts + 192, sts + 224, sts + 256, sts + 288,
              scr, x0, x3, tid);
    knn_stage(x2, xx, idx, scr, tid);
    edge_single(x2, x3, idx, P.W5, sts + 320, sts + 352, scr, x0, tid);

    // ---- W6 (512x96) + global max -> g[512]; 2 outputs per thread ----
    #pragma unroll 1
    for (int rep = 0; rep < 2; ++rep) {
        const int o = tid + rep * NTHR;
        u64 w[48];
        const ulonglong2* wr = (const ulonglong2*)(P.W6 + o * 96);
        #pragma unroll
        for (int q = 0; q < 24; ++q) { ulonglong2 v = __ldg(wr + q); w[2*q] = v.x; w[2*q+1] = v.y; }
        float gmax = -3.4e38f;
        for (int n = 0; n < NPT; ++n) {
            u64 s0 = 0, s1 = 0;
            const ulonglong2* a  = (const ulonglong2*)(x1 + n * XS);
            const ulonglong2* bb = (const ulonglong2*)(x2 + n * XS);
            const ulonglong2* cc = (const ulonglong2*)(x3 + n * XS);
            #pragma unroll
            for (int i = 0; i < 8; ++i) { ulonglong2 v = a[i];  fma2(s0, w[2*i],    v.x); fma2(s1, w[2*i+1],    v.y); }
            #pragma unroll
            for (int i = 0; i < 8; ++i) { ulonglong2 v = bb[i]; fma2(s0, w[16+2*i], v.x); fma2(s1, w[16+2*i+1], v.y); }
            #pragma unroll
            for (int i = 0; i < 8; ++i) { ulonglong2 v = cc[i]; fma2(s0, w[32+2*i], v.x); fma2(s1, w[32+2*i+1], v.y); }
            gmax = fmaxf(gmax, hsum(add2(s0, s1)));
        }
        gbuf[o] = lrelu(fmaf(__ldg(P.s[6] + o), gmax, __ldg(P.t[6] + o)));
    }
    __syncthreads();

    // ---- p[o] = W7[o,:512] . g ----
    if (tid < 128) {
        const ulonglong2* wr = (const ulonglong2*)(P.W7 + tid * 608);
        const ulonglong2* gv = (const ulonglong2*)gbuf;
        u64 s0 = 0, s1 = 0;
        #pragma unroll 16
        for (int q = 0; q < 128; ++q) {
            ulonglong2 wv = __ldg(wr + q); ulonglong2 g = gv[q];
            fma2(s0, wv.x, g.x); fma2(s1, wv.y, g.y);
        }
        pbuf[tid] = hsum(add2(s0, s1));
    }
    __syncthreads();

    // ---- h2[n][o] = lrelu(s7*(p[o] + W7[o,512:608].xc[n]) + t7) ----
    // h2 rows 0..77 in scr, rows 78..99 in x0 (both stride 132)
    {
        const int o = tid & 127, nh = tid >> 7;
        u64 w[48];
        const ulonglong2* wr = (const ulonglong2*)(P.W7 + o * 608 + 512);
        #pragma unroll
        for (int q = 0; q < 24; ++q) { ulonglong2 v = __ldg(wr + q); w[2*q] = v.x; w[2*q+1] = v.y; }
        const float po = pbuf[o];
        const float so = __ldg(P.s[7] + o), to = __ldg(P.t[7] + o);
        for (int n = nh * 50; n < nh * 50 + 50; ++n) {
            u64 s0 = 0, s1 = 0;
            const ulonglong2* a  = (const ulonglong2*)(x1 + n * XS);
            const ulonglong2* bb = (const ulonglong2*)(x2 + n * XS);
            const ulonglong2* cc = (const ulonglong2*)(x3 + n * XS);
            #pragma unroll
            for (int i = 0; i < 8; ++i) { ulonglong2 v = a[i];  fma2(s0, w[2*i],    v.x); fma2(s1, w[2*i+1],    v.y); }
            #pragma unroll
            for (int i = 0; i < 8; ++i) { ulonglong2 v = bb[i]; fma2(s0, w[16+2*i], v.x); fma2(s1, w[16+2*i+1], v.y); }
            #pragma unroll
            for (int i = 0; i < 8; ++i) { ulonglong2 v = cc[i]; fma2(s0, w[32+2*i], v.x); fma2(s1, w[32+2*i+1], v.y); }
            float* hr = (n < 78 ? scr + n * 132 : x0 + (n - 78) * 132);
            hr[o] = lrelu(fmaf(so, po + hsum(add2(s0, s1)), to));
        }
    }
    __syncthreads();

    // ---- stage W8 (padded stride 132) into x1/x2 region (dead now) ----
    {
        float* w8p = x1;
        for (int i = tid; i < 4096; i += NTHR) {
            int o2 = i >> 7, c = i & 127;
            w8p[o2 * 132 + c] = P.W8[i];
        }
    }
    __syncthreads();

    // ---- W8 (32x128): y8 -> x3 region ----
    {
        const float* w8p = x1;
        float* y8 = x3;
        const float s8v = __ldg(P.s[8] + (tid & 31));
        const float t8v = __ldg(P.t[8] + (tid & 31));
        for (int tt = tid; tt < 32 * NPT; tt += NTHR) {
            const int o2 = tt & 31, n = tt >> 5;
            const float* hr = (n < 78 ? scr + n * 132 : x0 + (n - 78) * 132);
            const ulonglong2* wr = (const ulonglong2*)(w8p + o2 * 132);
            const ulonglong2* hv = (const ulonglong2*)hr;
            u64 s0 = 0, s1 = 0;
            #pragma unroll
            for (int q = 0; q < 32; ++q) {
                ulonglong2 wv = wr[q]; ulonglong2 h = hv[q];
                fma2(s0, wv.x, h.x); fma2(s1, wv.y, h.y);
            }
            y8[n * XS + o2] = lrelu(fmaf(s8v, hsum(add2(s0, s1)), t8v));
        }
    }
    __syncthreads();

    // ---- final head ----
    if (tid < NPT) {
        u64 w[16];
        const ulonglong2* wr = (const ulonglong2*)P.W9;
        #pragma unroll
        for (int q = 0; q < 8; ++q) { ulonglong2 v = __ldg(wr + q); w[2*q] = v.x; w[2*q+1] = v.y; }
        out[b * NPT + tid] = dot32s(w, x3 + tid * XS);
    }
}

extern "C" void kernel_launch(void* const* d_in, const int* in_sizes, int n_in,
                              void* d_out, int out_size)
{
    Ptrs P;
    P.obs = (const float*)d_in[0];
    P.W0 = (const float*)d_in[1];  P.W1 = (const float*)d_in[2];
    P.W2 = (const float*)d_in[3];  P.W3 = (const float*)d_in[4];
    P.W4 = (const float*)d_in[5];  P.W5 = (const float*)d_in[6];
    P.W6 = (const float*)d_in[7];  P.W7 = (const float*)d_in[8];
    P.W8 = (const float*)d_in[9];  P.W9 = (const float*)d_in[10];

    const bool separated = (n_in > 17 && in_sizes[17] == 512);
    for (int i = 0; i < 9; ++i) {
        if (separated) {
            P.s[i] = (const float*)d_in[11 + i];
            P.t[i] = (const float*)d_in[20 + i];
        } else {
            P.s[i] = (const float*)d_in[11 + 2 * i];
            P.t[i] = (const float*)d_in[12 + 2 * i];
        }
    }

    const int B = in_sizes[0] / 3000;
    const int smem_bytes = 26952 * 4;   // 105.3 KB -> 2 CTAs/SM
    cudaFuncSetAttribute(dgcnn_fused, cudaFuncAttributeMaxDynamicSharedMemorySize, smem_bytes);
    dgcnn_fused<<<B, NTHR, smem_bytes>>>(P, (float*)d_out);
}